// round 16
// baseline (speedup 1.0000x reference)
#include <cuda_runtime.h>
#include <cuda_fp16.h>
#include <cstdint>
#include <math.h>

// Problem: B=2, S=2048, HID=2048, H=32, KVH=8, D=64, G=4, ROT=32
#define NBATCH 2
#define SEQ    2048
#define HID    2048
#define NHEAD  32
#define NKV    8
#define HDIM   64

// ---------------------------------------------------------------------------
// Scratch (device globals; no allocations allowed)
// ---------------------------------------------------------------------------
__device__ float g_q[NBATCH*SEQ*NHEAD*HDIM];
__device__ float g_k[NBATCH*SEQ*NKV*HDIM];
__device__ float g_v[NBATCH*SEQ*NKV*HDIM];

__device__ __half g_a16[4096*2048];     // hidden fp16
__device__ __half g_o16[4096*2048];     // attn out fp16
__device__ __half g_w16q[2048*2048];
__device__ __half g_w16k[512*2048];
__device__ __half g_w16v[512*2048];
__device__ __half g_w16o[2048*2048];
// fp16 attention operands
__device__ __half g_qh[NBATCH*SEQ*NHEAD*HDIM];
__device__ __half g_kh[NBATCH*SEQ*NKV*HDIM];
__device__ __half g_vht[NBATCH*NKV*HDIM*SEQ];   // [b][kvh][d][S]

// ---------------------------------------------------------------------------
// helpers
// ---------------------------------------------------------------------------
__device__ __forceinline__ void mma_f16(float* c, const uint32_t* a,
                                        uint32_t b0, uint32_t b1) {
    asm volatile(
        "mma.sync.aligned.m16n8k16.row.col.f32.f16.f16.f32 "
        "{%0,%1,%2,%3}, {%4,%5,%6,%7}, {%8,%9}, {%0,%1,%2,%3};"
        : "+f"(c[0]), "+f"(c[1]), "+f"(c[2]), "+f"(c[3])
        : "r"(a[0]), "r"(a[1]), "r"(a[2]), "r"(a[3]), "r"(b0), "r"(b1));
}
__device__ __forceinline__ void cp_async16(void* smem_dst, const void* gsrc) {
    uint32_t d;
    asm("{ .reg .u64 t; cvta.to.shared.u64 t, %1; cvt.u32.u64 %0, t; }"
        : "=r"(d) : "l"(smem_dst));
    asm volatile("cp.async.cg.shared.global [%0], [%1], 16;" :: "r"(d), "l"(gsrc));
}
#define CP_COMMIT() asm volatile("cp.async.commit_group;" ::: "memory")
#define CP_WAIT(n)  asm volatile("cp.async.wait_group %0;" :: "n"(n) : "memory")

__device__ __forceinline__ uint32_t pack_h2(float a, float b) {
    __half2 h = __floats2half2_rn(a, b);
    return *(uint32_t*)&h;
}

// ---------------------------------------------------------------------------
// fp32 -> fp16 with scale, vectorized x4
// ---------------------------------------------------------------------------
__global__ void tohalf_kernel(const float* __restrict__ x,
                              __half* __restrict__ y, int n4, float scale) {
    int i = blockIdx.x * blockDim.x + threadIdx.x;
    if (i >= n4) return;
    float4 v = ((const float4*)x)[i];
    __half2* yp = (__half2*)(y + (size_t)i * 4);
    yp[0] = __floats2half2_rn(v.x * scale, v.y * scale);
    yp[1] = __floats2half2_rn(v.z * scale, v.w * scale);
}

// ---------------------------------------------------------------------------
// Fused partial-RoPE + scale + fp16 convert.
// ---------------------------------------------------------------------------
__global__ void rope_half_kernel(const float* __restrict__ x,
                                 const float* __restrict__ ct,
                                 const float* __restrict__ st,
                                 __half* __restrict__ y,
                                 int nheads, int total4, float scale) {
    int idx = blockIdx.x * blockDim.x + threadIdx.x;
    if (idx >= total4) return;
    int qd = idx & 15;
    int bs = idx / (16 * nheads);
    float4 v = ((const float4*)x)[idx];
    float4 o = v;
    if (qd < 8) {
        int d0 = (qd & 3) * 4;
        float4 p = ((const float4*)x)[idx + (qd < 4 ? 4 : -4)];
        const float* cb = ct + bs * 32 + d0;
        const float* sb = st + bs * 32 + d0;
        if (qd < 4) {
            o.x = v.x * cb[0] - p.x * sb[0];
            o.y = v.y * cb[1] - p.y * sb[1];
            o.z = v.z * cb[2] - p.z * sb[2];
            o.w = v.w * cb[3] - p.w * sb[3];
        } else {
            o.x = v.x * cb[0] + p.x * sb[0];
            o.y = v.y * cb[1] + p.y * sb[1];
            o.z = v.z * cb[2] + p.z * sb[2];
            o.w = v.w * cb[3] + p.w * sb[3];
        }
    }
    __half2* yp = (__half2*)(y + (size_t)idx * 4);
    yp[0] = __floats2half2_rn(o.x * scale, o.y * scale);
    yp[1] = __floats2half2_rn(o.z * scale, o.w * scale);
}

// ---------------------------------------------------------------------------
// V transpose to fp16: v[b][s][kvh][d] fp32 -> vht[b][kvh][d][S] half
// ---------------------------------------------------------------------------
__global__ void vT_half_kernel(const float* __restrict__ v,
                               __half* __restrict__ vh) {
    __shared__ float t[32][33];
    const int bkv = blockIdx.z;
    const int b = bkv / NKV, kvh = bkv % NKV;
    const int s0 = blockIdx.x * 32, d0 = blockIdx.y * 32;
    const int tx = threadIdx.x, ty = threadIdx.y;
#pragma unroll
    for (int j = 0; j < 32; j += 8) {
        int s = s0 + ty + j;
        t[ty + j][tx] = v[((size_t)(b * SEQ + s) * NKV + kvh) * HDIM + d0 + tx];
    }
    __syncthreads();
#pragma unroll
    for (int j = 0; j < 32; j += 8) {
        int d = d0 + ty + j;
        size_t o = ((size_t)(b * NKV + kvh) * HDIM + d) * SEQ + s0 + tx;
        vh[o] = __float2half_rn(t[tx][ty + j]);
    }
}

// ---------------------------------------------------------------------------
// Tensor-core GEMM, single-term fp16: C = A @ B^T.  (R12 proven, untouched)
// ---------------------------------------------------------------------------
#define LDS_STRIDE 40
#define ARR_BYTES  (128 * LDS_STRIDE * 2)     // 10240
#define STAGE_BYTES (2 * ARR_BYTES)           // 20480
#define GEMM_SMEM  (2 * STAGE_BYTES)          // 40960

__global__ __launch_bounds__(256)
void gemm_mma16(const __half* __restrict__ A, const __half* __restrict__ B,
                float* __restrict__ C, int M, int N, int K) {
    extern __shared__ char smem[];

    const int tid = threadIdx.x;
    const int wid = tid >> 5;
    const int lane = tid & 31;
    const int wm = (wid >> 2) * 64;
    const int wn = (wid & 3) * 32;
    const int lr = lane >> 2;
    const int lk = (lane & 3) * 2;

    const int bm = blockIdx.y * 128;
    const int bn = blockIdx.x * 128;

    const int l_row0 = tid >> 2;
    const int l_cw   = (tid & 3) * 8;

    auto stage_ptr = [&](int s, int arr) -> char* {
        return smem + s * STAGE_BYTES + arr * ARR_BYTES;
    };

    auto prefetch = [&](int s, int k0) {
        const __half* gsrc[2] = {A, B};
#pragma unroll
        for (int t = 0; t < 2; t++) {
            const int rb = (t == 0) ? bm : bn;
            char* base = stage_ptr(s, t);
#pragma unroll
            for (int u = 0; u < 2; u++) {
                int row = l_row0 + u * 64;
                cp_async16(base + row * (LDS_STRIDE * 2) + l_cw * 2,
                           gsrc[t] + (size_t)(rb + row) * K + k0 + l_cw);
            }
        }
        CP_COMMIT();
    };

    float acc[4][4][4];
#pragma unroll
    for (int mi = 0; mi < 4; mi++)
#pragma unroll
        for (int ni = 0; ni < 4; ni++)
#pragma unroll
            for (int r = 0; r < 4; r++) acc[mi][ni][r] = 0.f;

    const int nchunk = K / 32;
    prefetch(0, 0);

    for (int ch = 0; ch < nchunk; ch++) {
        const int s = ch & 1;
        if (ch + 1 < nchunk) {
            prefetch(s ^ 1, (ch + 1) * 32);
            CP_WAIT(1);
        } else {
            CP_WAIT(0);
        }
        __syncthreads();

        const __half* sA = (const __half*)stage_ptr(s, 0);
        const __half* sB = (const __half*)stage_ptr(s, 1);

#pragma unroll
        for (int kk = 0; kk < 2; kk++) {
            const int k0 = kk * 16;
            uint32_t bf[4][2];
#pragma unroll
            for (int ni = 0; ni < 4; ni++) {
                int n = wn + ni * 8 + lr;
                bf[ni][0] = *(const uint32_t*)&sB[n * LDS_STRIDE + k0 + lk];
                bf[ni][1] = *(const uint32_t*)&sB[n * LDS_STRIDE + k0 + lk + 8];
            }
#pragma unroll
            for (int mi = 0; mi < 4; mi++) {
                int r0 = wm + mi * 16 + lr;
                uint32_t af[4];
                af[0] = *(const uint32_t*)&sA[(r0    ) * LDS_STRIDE + k0 + lk];
                af[1] = *(const uint32_t*)&sA[(r0 + 8) * LDS_STRIDE + k0 + lk];
                af[2] = *(const uint32_t*)&sA[(r0    ) * LDS_STRIDE + k0 + lk + 8];
                af[3] = *(const uint32_t*)&sA[(r0 + 8) * LDS_STRIDE + k0 + lk + 8];
#pragma unroll
                for (int ni = 0; ni < 4; ni++)
                    mma_f16(acc[mi][ni], af, bf[ni][0], bf[ni][1]);
            }
        }
        __syncthreads();
    }

#pragma unroll
    for (int mi = 0; mi < 4; mi++) {
        int row = bm + wm + mi * 16 + lr;
#pragma unroll
        for (int ni = 0; ni < 4; ni++) {
            int col = bn + wn + ni * 8 + lk;
            *(float2*)(C + (size_t)row * N + col) =
                make_float2(acc[mi][ni][0], acc[mi][ni][1]);
            *(float2*)(C + (size_t)(row + 8) * N + col) =
                make_float2(acc[mi][ni][2], acc[mi][ni][3]);
        }
    }
}

// ---------------------------------------------------------------------------
// Flash attention, FA2-style register softmax (fp16 single-term MMA).
// Grid (32, 64). 128 threads, 4 warps; warp owns 16 q-rows x all 64 keys.
// Row stats + P live in registers; shfl_xor(1,2) reduces within the quad.
// 2-stage K/V pipeline. Smem: Q + 2K + 2V only.
// ---------------------------------------------------------------------------
#define KSTR  72
#define NEGBIG (-1e30f)
#define FLASH_SMEM (5 * 64 * KSTR * 2)

__global__ __launch_bounds__(128)
void flash_tc(const __half* __restrict__ qg, const __half* __restrict__ kg,
              const __half* __restrict__ vg, __half* __restrict__ og) {
    extern __shared__ char smc[];
    __half* sQ  = (__half*)smc;
    __half* sK0 = sQ  + 64 * KSTR;
    __half* sK1 = sK0 + 64 * KSTR;
    __half* sV0 = sK1 + 64 * KSTR;
    __half* sV1 = sV0 + 64 * KSTR;

    const int tid  = threadIdx.x;
    const int wid  = tid >> 5;
    const int lane = tid & 31;
    const int wm = wid * 16;
    const int lr = lane >> 2;
    const int lk = (lane & 3) * 2;

    const int qt  = gridDim.x - 1 - blockIdx.x;
    const int bh  = blockIdx.y;
    const int b   = bh >> 5;
    const int h   = bh & 31;
    const int kvh = h >> 2;

    // Q load: 64 rows x 8 chunks = 512 / 128 threads = 4 each
#pragma unroll
    for (int u = 0; u < 4; u++) {
        int sl = tid + 128 * u;
        int row = sl >> 3, cw = (sl & 7) * 8;
        cp_async16(sQ + row * KSTR + cw,
                   qg + ((size_t)(b * SEQ + qt * 64 + row) * NHEAD + h) * HDIM + cw);
    }
    CP_COMMIT();

    auto loadKV = [&](int kt, int s) {
        __half* dK = s ? sK1 : sK0;
        __half* dV = s ? sV1 : sV0;
#pragma unroll
        for (int u = 0; u < 4; u++) {
            int sl = tid + 128 * u;
            int row = sl >> 3, cw = (sl & 7) * 8;
            cp_async16(dK + row * KSTR + cw,
                       kg + ((size_t)(b * SEQ + kt * 64 + row) * NKV + kvh) * HDIM + cw);
            cp_async16(dV + row * KSTR + cw,
                       vg + ((size_t)(b * NKV + kvh) * HDIM + row) * SEQ + kt * 64 + cw);
        }
        CP_COMMIT();
    };
    loadKV(0, 0);

    float m0 = NEGBIG, m1 = NEGBIG, l0 = 0.f, l1 = 0.f;
    float oacc[8][4];
#pragma unroll
    for (int nb = 0; nb < 8; nb++)
#pragma unroll
        for (int r = 0; r < 4; r++) oacc[nb][r] = 0.f;

    for (int kt = 0; kt <= qt; kt++) {
        const int s = kt & 1;
        if (kt + 1 <= qt) {
            loadKV(kt + 1, s ^ 1);
            CP_WAIT(1);
        } else {
            CP_WAIT(0);
        }
        __syncthreads();

        const __half* sK = s ? sK1 : sK0;
        const __half* sV = s ? sV1 : sV0;

        // ---- S = Q @ K^T : warp rows wm..wm+15, all 64 keys (8 n-blocks) ----
        float sacc[8][4];
#pragma unroll
        for (int nb = 0; nb < 8; nb++)
#pragma unroll
            for (int r = 0; r < 4; r++) sacc[nb][r] = 0.f;

#pragma unroll
        for (int kk = 0; kk < 4; kk++) {
            const int k0 = kk * 16;
            uint32_t qa[4];
            qa[0] = *(const uint32_t*)&sQ[(wm + lr    ) * KSTR + k0 + lk];
            qa[1] = *(const uint32_t*)&sQ[(wm + lr + 8) * KSTR + k0 + lk];
            qa[2] = *(const uint32_t*)&sQ[(wm + lr    ) * KSTR + k0 + lk + 8];
            qa[3] = *(const uint32_t*)&sQ[(wm + lr + 8) * KSTR + k0 + lk + 8];
#pragma unroll
            for (int nb = 0; nb < 8; nb++) {
                uint32_t b0 = *(const uint32_t*)&sK[(nb * 8 + lr) * KSTR + k0 + lk];
                uint32_t b1 = *(const uint32_t*)&sK[(nb * 8 + lr) * KSTR + k0 + lk + 8];
                mma_f16(sacc[nb], qa, b0, b1);
            }
        }

        // ---- causal mask (diag tile only) ----
        if (kt == qt) {
            const int r0 = wm + lr, r1 = r0 + 8;
#pragma unroll
            for (int nb = 0; nb < 8; nb++) {
                int c = nb * 8 + lk;
                if (c     > r0) sacc[nb][0] = NEGBIG;
                if (c + 1 > r0) sacc[nb][1] = NEGBIG;
                if (c     > r1) sacc[nb][2] = NEGBIG;
                if (c + 1 > r1) sacc[nb][3] = NEGBIG;
            }
        }

        // ---- register online softmax (quad shfl reduction) ----
        float mx0 = NEGBIG, mx1 = NEGBIG;
#pragma unroll
        for (int nb = 0; nb < 8; nb++) {
            mx0 = fmaxf(mx0, fmaxf(sacc[nb][0], sacc[nb][1]));
            mx1 = fmaxf(mx1, fmaxf(sacc[nb][2], sacc[nb][3]));
        }
        mx0 = fmaxf(mx0, __shfl_xor_sync(0xFFFFFFFF, mx0, 1));
        mx0 = fmaxf(mx0, __shfl_xor_sync(0xFFFFFFFF, mx0, 2));
        mx1 = fmaxf(mx1, __shfl_xor_sync(0xFFFFFFFF, mx1, 1));
        mx1 = fmaxf(mx1, __shfl_xor_sync(0xFFFFFFFF, mx1, 2));
        const float mn0 = fmaxf(m0, mx0);
        const float mn1 = fmaxf(m1, mx1);
        const float al0 = __expf(m0 - mn0);
        const float al1 = __expf(m1 - mn1);
        float sum0 = 0.f, sum1 = 0.f;
#pragma unroll
        for (int nb = 0; nb < 8; nb++) {
            sacc[nb][0] = __expf(sacc[nb][0] - mn0);
            sacc[nb][1] = __expf(sacc[nb][1] - mn0);
            sacc[nb][2] = __expf(sacc[nb][2] - mn1);
            sacc[nb][3] = __expf(sacc[nb][3] - mn1);
            sum0 += sacc[nb][0] + sacc[nb][1];
            sum1 += sacc[nb][2] + sacc[nb][3];
        }
        sum0 += __shfl_xor_sync(0xFFFFFFFF, sum0, 1);
        sum0 += __shfl_xor_sync(0xFFFFFFFF, sum0, 2);
        sum1 += __shfl_xor_sync(0xFFFFFFFF, sum1, 1);
        sum1 += __shfl_xor_sync(0xFFFFFFFF, sum1, 2);
        l0 = l0 * al0 + sum0;
        l1 = l1 * al1 + sum1;
        m0 = mn0;
        m1 = mn1;

        // ---- rescale O, accumulate P @ V (P fragments built in registers) ----
#pragma unroll
        for (int nb = 0; nb < 8; nb++) {
            oacc[nb][0] *= al0; oacc[nb][1] *= al0;
            oacc[nb][2] *= al1; oacc[nb][3] *= al1;
        }
#pragma unroll
        for (int kk = 0; kk < 4; kk++) {
            const int k0 = kk * 16;
            uint32_t pa[4];
            pa[0] = pack_h2(sacc[2 * kk][0],     sacc[2 * kk][1]);
            pa[1] = pack_h2(sacc[2 * kk][2],     sacc[2 * kk][3]);
            pa[2] = pack_h2(sacc[2 * kk + 1][0], sacc[2 * kk + 1][1]);
            pa[3] = pack_h2(sacc[2 * kk + 1][2], sacc[2 * kk + 1][3]);
#pragma unroll
            for (int nb = 0; nb < 8; nb++) {
                uint32_t b0 = *(const uint32_t*)&sV[(nb * 8 + lr) * KSTR + k0 + lk];
                uint32_t b1 = *(const uint32_t*)&sV[(nb * 8 + lr) * KSTR + k0 + lk + 8];
                mma_f16(oacc[nb], pa, b0, b1);
            }
        }
        __syncthreads();
    }

    // ---- normalize + write fp16 output [b][s][h][d] ----
    const float inv0 = 1.f / l0;
    const float inv1 = 1.f / l1;
#pragma unroll
    for (int nb = 0; nb < 8; nb++) {
        int c = nb * 8 + lk;
        size_t o0 = ((size_t)(b * SEQ + qt * 64 + wm + lr) * NHEAD + h) * HDIM + c;
        size_t o1 = ((size_t)(b * SEQ + qt * 64 + wm + lr + 8) * NHEAD + h) * HDIM + c;
        *(__half2*)(og + o0) = __floats2half2_rn(oacc[nb][0] * inv0,
                                                 oacc[nb][1] * inv0);
        *(__half2*)(og + o1) = __floats2half2_rn(oacc[nb][2] * inv1,
                                                 oacc[nb][3] * inv1);
    }
}

// ---------------------------------------------------------------------------
// Host launcher
// Inputs: 0 hidden 1 cos 2 sin 3 mask(unused) 4 Wq 5 Wk 6 Wv 7 Wo
// ---------------------------------------------------------------------------
extern "C" void kernel_launch(void* const* d_in, const int* in_sizes, int n_in,
                              void* d_out, int out_size) {
    const float* hidden = (const float*)d_in[0];
    const float* cosb   = (const float*)d_in[1];
    const float* sinb   = (const float*)d_in[2];
    const float* Wq     = (const float*)d_in[4];
    const float* Wk     = (const float*)d_in[5];
    const float* Wv     = (const float*)d_in[6];
    const float* Wo     = (const float*)d_in[7];
    float* out = (float*)d_out;

    float *qp, *kp, *vp;
    cudaGetSymbolAddress((void**)&qp, g_q);
    cudaGetSymbolAddress((void**)&kp, g_k);
    cudaGetSymbolAddress((void**)&vp, g_v);

    __half *a16, *o16, *w16q, *w16k, *w16v, *w16o, *qhp, *khp, *vhtp;
    cudaGetSymbolAddress((void**)&a16, g_a16);
    cudaGetSymbolAddress((void**)&o16, g_o16);
    cudaGetSymbolAddress((void**)&w16q, g_w16q);
    cudaGetSymbolAddress((void**)&w16k, g_w16k);
    cudaGetSymbolAddress((void**)&w16v, g_w16v);
    cudaGetSymbolAddress((void**)&w16o, g_w16o);
    cudaGetSymbolAddress((void**)&qhp, g_qh);
    cudaGetSymbolAddress((void**)&khp, g_kh);
    cudaGetSymbolAddress((void**)&vhtp, g_vht);

    const int M = NBATCH * SEQ;  // 4096

    cudaFuncSetAttribute(gemm_mma16, cudaFuncAttributeMaxDynamicSharedMemorySize,
                         GEMM_SMEM);
    cudaFuncSetAttribute(flash_tc, cudaFuncAttributeMaxDynamicSharedMemorySize,
                         FLASH_SMEM);

    // Operand conversions (all single fp16)
    int n4h = (M * HID) / 4;
    tohalf_kernel<<<(n4h + 255) / 256, 256>>>(hidden, a16, n4h, 1.f);
    int n4q = (2048 * 2048) / 4;
    tohalf_kernel<<<(n4q + 255) / 256, 256>>>(Wq, w16q, n4q, 1.f);
    tohalf_kernel<<<(n4q + 255) / 256, 256>>>(Wo, w16o, n4q, 1.f);
    int n4k = (512 * 2048) / 4;
    tohalf_kernel<<<(n4k + 255) / 256, 256>>>(Wk, w16k, n4k, 1.f);
    tohalf_kernel<<<(n4k + 255) / 256, 256>>>(Wv, w16v, n4k, 1.f);

    // QKV projections (fp16 single-term, fp32 out)
    gemm_mma16<<<dim3(2048 / 128, M / 128), 256, GEMM_SMEM>>>(a16, w16q, qp, M, 2048, 2048);
    gemm_mma16<<<dim3(512  / 128, M / 128), 256, GEMM_SMEM>>>(a16, w16k, kp, M, 512, 2048);
    gemm_mma16<<<dim3(512  / 128, M / 128), 256, GEMM_SMEM>>>(a16, w16v, vp, M, 512, 2048);

    // Fused RoPE + scale + fp16 convert (Q scaled by 1/sqrt(D))
    int tq4 = M * NHEAD * 16;
    rope_half_kernel<<<(tq4 + 255) / 256, 256>>>(qp, cosb, sinb, qhp, NHEAD, tq4, 0.125f);
    int tk4 = M * NKV * 16;
    rope_half_kernel<<<(tk4 + 255) / 256, 256>>>(kp, cosb, sinb, khp, NKV, tk4, 1.f);

    vT_half_kernel<<<dim3(SEQ / 32, HDIM / 32, NBATCH * NKV), dim3(32, 8)>>>(vp, vhtp);

    // FA2-style register-softmax flash attention -> fp16 out
    flash_tc<<<dim3(SEQ / 64, NBATCH * NHEAD), 128, FLASH_SMEM>>>(qhp, khp, vhtp, o16);

    // Output projection (fp16 single-term)
    gemm_mma16<<<dim3(2048 / 128, M / 128), 256, GEMM_SMEM>>>(o16, w16o, out, M, 2048, 2048);
}

// round 17
// speedup vs baseline: 1.5189x; 1.5189x over previous
#include <cuda_runtime.h>
#include <cuda_fp16.h>
#include <cstdint>
#include <math.h>

// Problem: B=2, S=2048, HID=2048, H=32, KVH=8, D=64, G=4, ROT=32
#define NBATCH 2
#define SEQ    2048
#define HID    2048
#define NHEAD  32
#define NKV    8
#define HDIM   64

// ---------------------------------------------------------------------------
// Scratch (device globals; no allocations allowed)
// ---------------------------------------------------------------------------
__device__ float g_q[NBATCH*SEQ*NHEAD*HDIM];
__device__ float g_k[NBATCH*SEQ*NKV*HDIM];
__device__ float g_v[NBATCH*SEQ*NKV*HDIM];

__device__ __half g_a16[4096*2048];     // hidden fp16
__device__ __half g_o16[4096*2048];     // attn out fp16
__device__ __half g_w16q[2048*2048];
__device__ __half g_w16k[512*2048];
__device__ __half g_w16v[512*2048];
__device__ __half g_w16o[2048*2048];
// fp16 attention operands
__device__ __half g_qh[NBATCH*SEQ*NHEAD*HDIM];
__device__ __half g_kh[NBATCH*SEQ*NKV*HDIM];
__device__ __half g_vht[NBATCH*NKV*HDIM*SEQ];   // [b][kvh][d][S]

// ---------------------------------------------------------------------------
// helpers
// ---------------------------------------------------------------------------
__device__ __forceinline__ void mma_f16(float* c, const uint32_t* a,
                                        uint32_t b0, uint32_t b1) {
    asm volatile(
        "mma.sync.aligned.m16n8k16.row.col.f32.f16.f16.f32 "
        "{%0,%1,%2,%3}, {%4,%5,%6,%7}, {%8,%9}, {%0,%1,%2,%3};"
        : "+f"(c[0]), "+f"(c[1]), "+f"(c[2]), "+f"(c[3])
        : "r"(a[0]), "r"(a[1]), "r"(a[2]), "r"(a[3]), "r"(b0), "r"(b1));
}
__device__ __forceinline__ void cp_async16(void* smem_dst, const void* gsrc) {
    uint32_t d;
    asm("{ .reg .u64 t; cvta.to.shared.u64 t, %1; cvt.u32.u64 %0, t; }"
        : "=r"(d) : "l"(smem_dst));
    asm volatile("cp.async.cg.shared.global [%0], [%1], 16;" :: "r"(d), "l"(gsrc));
}
#define CP_COMMIT() asm volatile("cp.async.commit_group;" ::: "memory")
#define CP_WAIT(n)  asm volatile("cp.async.wait_group %0;" :: "n"(n) : "memory")

__device__ __forceinline__ uint32_t pack_h2(float a, float b) {
    __half2 h = __floats2half2_rn(a, b);
    return *(uint32_t*)&h;
}

// ---------------------------------------------------------------------------
// fp32 -> fp16 with scale, vectorized x4
// ---------------------------------------------------------------------------
__global__ void tohalf_kernel(const float* __restrict__ x,
                              __half* __restrict__ y, int n4, float scale) {
    int i = blockIdx.x * blockDim.x + threadIdx.x;
    if (i >= n4) return;
    float4 v = ((const float4*)x)[i];
    __half2* yp = (__half2*)(y + (size_t)i * 4);
    yp[0] = __floats2half2_rn(v.x * scale, v.y * scale);
    yp[1] = __floats2half2_rn(v.z * scale, v.w * scale);
}

// ---------------------------------------------------------------------------
// Fused partial-RoPE + scale + fp16 convert.
// ---------------------------------------------------------------------------
__global__ void rope_half_kernel(const float* __restrict__ x,
                                 const float* __restrict__ ct,
                                 const float* __restrict__ st,
                                 __half* __restrict__ y,
                                 int nheads, int total4, float scale) {
    int idx = blockIdx.x * blockDim.x + threadIdx.x;
    if (idx >= total4) return;
    int qd = idx & 15;
    int bs = idx / (16 * nheads);
    float4 v = ((const float4*)x)[idx];
    float4 o = v;
    if (qd < 8) {
        int d0 = (qd & 3) * 4;
        float4 p = ((const float4*)x)[idx + (qd < 4 ? 4 : -4)];
        const float* cb = ct + bs * 32 + d0;
        const float* sb = st + bs * 32 + d0;
        if (qd < 4) {
            o.x = v.x * cb[0] - p.x * sb[0];
            o.y = v.y * cb[1] - p.y * sb[1];
            o.z = v.z * cb[2] - p.z * sb[2];
            o.w = v.w * cb[3] - p.w * sb[3];
        } else {
            o.x = v.x * cb[0] + p.x * sb[0];
            o.y = v.y * cb[1] + p.y * sb[1];
            o.z = v.z * cb[2] + p.z * sb[2];
            o.w = v.w * cb[3] + p.w * sb[3];
        }
    }
    __half2* yp = (__half2*)(y + (size_t)idx * 4);
    yp[0] = __floats2half2_rn(o.x * scale, o.y * scale);
    yp[1] = __floats2half2_rn(o.z * scale, o.w * scale);
}

// ---------------------------------------------------------------------------
// V transpose to fp16: v[b][s][kvh][d] fp32 -> vht[b][kvh][d][S] half
// ---------------------------------------------------------------------------
__global__ void vT_half_kernel(const float* __restrict__ v,
                               __half* __restrict__ vh) {
    __shared__ float t[32][33];
    const int bkv = blockIdx.z;
    const int b = bkv / NKV, kvh = bkv % NKV;
    const int s0 = blockIdx.x * 32, d0 = blockIdx.y * 32;
    const int tx = threadIdx.x, ty = threadIdx.y;
#pragma unroll
    for (int j = 0; j < 32; j += 8) {
        int s = s0 + ty + j;
        t[ty + j][tx] = v[((size_t)(b * SEQ + s) * NKV + kvh) * HDIM + d0 + tx];
    }
    __syncthreads();
#pragma unroll
    for (int j = 0; j < 32; j += 8) {
        int d = d0 + ty + j;
        size_t o = ((size_t)(b * NKV + kvh) * HDIM + d) * SEQ + s0 + tx;
        vh[o] = __float2half_rn(t[tx][ty + j]);
    }
}

// ---------------------------------------------------------------------------
// Tensor-core GEMM, single-term fp16: C = A @ B^T.  (R12 proven, untouched)
// ---------------------------------------------------------------------------
#define LDS_STRIDE 40
#define ARR_BYTES  (128 * LDS_STRIDE * 2)     // 10240
#define STAGE_BYTES (2 * ARR_BYTES)           // 20480
#define GEMM_SMEM  (2 * STAGE_BYTES)          // 40960

__global__ __launch_bounds__(256)
void gemm_mma16(const __half* __restrict__ A, const __half* __restrict__ B,
                float* __restrict__ C, int M, int N, int K) {
    extern __shared__ char smem[];

    const int tid = threadIdx.x;
    const int wid = tid >> 5;
    const int lane = tid & 31;
    const int wm = (wid >> 2) * 64;
    const int wn = (wid & 3) * 32;
    const int lr = lane >> 2;
    const int lk = (lane & 3) * 2;

    const int bm = blockIdx.y * 128;
    const int bn = blockIdx.x * 128;

    const int l_row0 = tid >> 2;
    const int l_cw   = (tid & 3) * 8;

    auto stage_ptr = [&](int s, int arr) -> char* {
        return smem + s * STAGE_BYTES + arr * ARR_BYTES;
    };

    auto prefetch = [&](int s, int k0) {
        const __half* gsrc[2] = {A, B};
#pragma unroll
        for (int t = 0; t < 2; t++) {
            const int rb = (t == 0) ? bm : bn;
            char* base = stage_ptr(s, t);
#pragma unroll
            for (int u = 0; u < 2; u++) {
                int row = l_row0 + u * 64;
                cp_async16(base + row * (LDS_STRIDE * 2) + l_cw * 2,
                           gsrc[t] + (size_t)(rb + row) * K + k0 + l_cw);
            }
        }
        CP_COMMIT();
    };

    float acc[4][4][4];
#pragma unroll
    for (int mi = 0; mi < 4; mi++)
#pragma unroll
        for (int ni = 0; ni < 4; ni++)
#pragma unroll
            for (int r = 0; r < 4; r++) acc[mi][ni][r] = 0.f;

    const int nchunk = K / 32;
    prefetch(0, 0);

    for (int ch = 0; ch < nchunk; ch++) {
        const int s = ch & 1;
        if (ch + 1 < nchunk) {
            prefetch(s ^ 1, (ch + 1) * 32);
            CP_WAIT(1);
        } else {
            CP_WAIT(0);
        }
        __syncthreads();

        const __half* sA = (const __half*)stage_ptr(s, 0);
        const __half* sB = (const __half*)stage_ptr(s, 1);

#pragma unroll
        for (int kk = 0; kk < 2; kk++) {
            const int k0 = kk * 16;
            uint32_t bf[4][2];
#pragma unroll
            for (int ni = 0; ni < 4; ni++) {
                int n = wn + ni * 8 + lr;
                bf[ni][0] = *(const uint32_t*)&sB[n * LDS_STRIDE + k0 + lk];
                bf[ni][1] = *(const uint32_t*)&sB[n * LDS_STRIDE + k0 + lk + 8];
            }
#pragma unroll
            for (int mi = 0; mi < 4; mi++) {
                int r0 = wm + mi * 16 + lr;
                uint32_t af[4];
                af[0] = *(const uint32_t*)&sA[(r0    ) * LDS_STRIDE + k0 + lk];
                af[1] = *(const uint32_t*)&sA[(r0 + 8) * LDS_STRIDE + k0 + lk];
                af[2] = *(const uint32_t*)&sA[(r0    ) * LDS_STRIDE + k0 + lk + 8];
                af[3] = *(const uint32_t*)&sA[(r0 + 8) * LDS_STRIDE + k0 + lk + 8];
#pragma unroll
                for (int ni = 0; ni < 4; ni++)
                    mma_f16(acc[mi][ni], af, bf[ni][0], bf[ni][1]);
            }
        }
        __syncthreads();
    }

#pragma unroll
    for (int mi = 0; mi < 4; mi++) {
        int row = bm + wm + mi * 16 + lr;
#pragma unroll
        for (int ni = 0; ni < 4; ni++) {
            int col = bn + wn + ni * 8 + lk;
            *(float2*)(C + (size_t)row * N + col) =
                make_float2(acc[mi][ni][0], acc[mi][ni][1]);
            *(float2*)(C + (size_t)(row + 8) * N + col) =
                make_float2(acc[mi][ni][2], acc[mi][ni][3]);
        }
    }
}

// ---------------------------------------------------------------------------
// Flash attention, FA2-style register softmax, 128-row Q tile, 8 warps.
// Grid (16, 64). 256 threads; warp w owns q-rows [w*16, w*16+16) of the
// 128-row tile, all 64 keys of each K tile. Inner loop identical to the
// numerically-proven R16 core. 2-stage K/V pipeline.
// ---------------------------------------------------------------------------
#define KSTR  72
#define NEGBIG (-1e30f)
// smem: Q(128 rows) + 2K(64) + 2V(64)
#define FLASH_SMEM ((128 + 4 * 64) * KSTR * 2)

__global__ __launch_bounds__(256)
void flash_tc(const __half* __restrict__ qg, const __half* __restrict__ kg,
              const __half* __restrict__ vg, __half* __restrict__ og) {
    extern __shared__ char smc[];
    __half* sQ  = (__half*)smc;              // 128 rows
    __half* sK0 = sQ  + 128 * KSTR;
    __half* sK1 = sK0 + 64 * KSTR;
    __half* sV0 = sK1 + 64 * KSTR;
    __half* sV1 = sV0 + 64 * KSTR;

    const int tid  = threadIdx.x;
    const int wid  = tid >> 5;
    const int lane = tid & 31;
    const int wm = wid * 16;                 // warp's q-row base within tile
    const int lr = lane >> 2;
    const int lk = (lane & 3) * 2;

    const int qt  = gridDim.x - 1 - blockIdx.x;   // 128-row q tile index
    const int bh  = blockIdx.y;
    const int b   = bh >> 5;
    const int h   = bh & 31;
    const int kvh = h >> 2;
    const int nkt = 2 * qt + 2;              // number of 64-key tiles

    // Q load: 128 rows x 8 chunks = 1024 slots / 256 threads = 4 each
#pragma unroll
    for (int u = 0; u < 4; u++) {
        int sl = tid + 256 * u;
        int row = sl >> 3, cw = (sl & 7) * 8;
        cp_async16(sQ + row * KSTR + cw,
                   qg + ((size_t)(b * SEQ + qt * 128 + row) * NHEAD + h) * HDIM + cw);
    }
    CP_COMMIT();

    auto loadKV = [&](int kt, int s) {
        __half* dK = s ? sK1 : sK0;
        __half* dV = s ? sV1 : sV0;
#pragma unroll
        for (int u = 0; u < 2; u++) {
            int sl = tid + 256 * u;
            int row = sl >> 3, cw = (sl & 7) * 8;
            cp_async16(dK + row * KSTR + cw,
                       kg + ((size_t)(b * SEQ + kt * 64 + row) * NKV + kvh) * HDIM + cw);
            cp_async16(dV + row * KSTR + cw,
                       vg + ((size_t)(b * NKV + kvh) * HDIM + row) * SEQ + kt * 64 + cw);
        }
        CP_COMMIT();
    };
    loadKV(0, 0);

    float m0 = NEGBIG, m1 = NEGBIG, l0 = 0.f, l1 = 0.f;
    float oacc[8][4];
#pragma unroll
    for (int nb = 0; nb < 8; nb++)
#pragma unroll
        for (int r = 0; r < 4; r++) oacc[nb][r] = 0.f;

    for (int kt = 0; kt < nkt; kt++) {
        const int s = kt & 1;
        if (kt + 1 < nkt) {
            loadKV(kt + 1, s ^ 1);
            CP_WAIT(1);
        } else {
            CP_WAIT(0);
        }
        __syncthreads();

        const __half* sK = s ? sK1 : sK0;
        const __half* sV = s ? sV1 : sV0;

        // ---- S = Q @ K^T : warp rows wm..wm+15, all 64 keys ----
        float sacc[8][4];
#pragma unroll
        for (int nb = 0; nb < 8; nb++)
#pragma unroll
            for (int r = 0; r < 4; r++) sacc[nb][r] = 0.f;

#pragma unroll
        for (int kk = 0; kk < 4; kk++) {
            const int k0 = kk * 16;
            uint32_t qa[4];
            qa[0] = *(const uint32_t*)&sQ[(wm + lr    ) * KSTR + k0 + lk];
            qa[1] = *(const uint32_t*)&sQ[(wm + lr + 8) * KSTR + k0 + lk];
            qa[2] = *(const uint32_t*)&sQ[(wm + lr    ) * KSTR + k0 + lk + 8];
            qa[3] = *(const uint32_t*)&sQ[(wm + lr + 8) * KSTR + k0 + lk + 8];
#pragma unroll
            for (int nb = 0; nb < 8; nb++) {
                uint32_t b0 = *(const uint32_t*)&sK[(nb * 8 + lr) * KSTR + k0 + lk];
                uint32_t b1 = *(const uint32_t*)&sK[(nb * 8 + lr) * KSTR + k0 + lk + 8];
                mma_f16(sacc[nb], qa, b0, b1);
            }
        }

        // ---- causal mask: global row vs global col ----
        {
            const int gr0 = qt * 128 + wm + lr;
            const int gr1 = gr0 + 8;
            const int gc0 = kt * 64 + lk;
            if (gc0 + 63 > gr0) {   // tile may need masking for this thread's rows
#pragma unroll
                for (int nb = 0; nb < 8; nb++) {
                    int c = gc0 + nb * 8;
                    if (c     > gr0) sacc[nb][0] = NEGBIG;
                    if (c + 1 > gr0) sacc[nb][1] = NEGBIG;
                    if (c     > gr1) sacc[nb][2] = NEGBIG;
                    if (c + 1 > gr1) sacc[nb][3] = NEGBIG;
                }
            }
        }

        // ---- register online softmax (quad shfl reduction) ----
        float mx0 = NEGBIG, mx1 = NEGBIG;
#pragma unroll
        for (int nb = 0; nb < 8; nb++) {
            mx0 = fmaxf(mx0, fmaxf(sacc[nb][0], sacc[nb][1]));
            mx1 = fmaxf(mx1, fmaxf(sacc[nb][2], sacc[nb][3]));
        }
        mx0 = fmaxf(mx0, __shfl_xor_sync(0xFFFFFFFF, mx0, 1));
        mx0 = fmaxf(mx0, __shfl_xor_sync(0xFFFFFFFF, mx0, 2));
        mx1 = fmaxf(mx1, __shfl_xor_sync(0xFFFFFFFF, mx1, 1));
        mx1 = fmaxf(mx1, __shfl_xor_sync(0xFFFFFFFF, mx1, 2));
        const float mn0 = fmaxf(m0, mx0);
        const float mn1 = fmaxf(m1, mx1);
        const float al0 = __expf(m0 - mn0);
        const float al1 = __expf(m1 - mn1);
        float sum0 = 0.f, sum1 = 0.f;
#pragma unroll
        for (int nb = 0; nb < 8; nb++) {
            sacc[nb][0] = __expf(sacc[nb][0] - mn0);
            sacc[nb][1] = __expf(sacc[nb][1] - mn0);
            sacc[nb][2] = __expf(sacc[nb][2] - mn1);
            sacc[nb][3] = __expf(sacc[nb][3] - mn1);
            sum0 += sacc[nb][0] + sacc[nb][1];
            sum1 += sacc[nb][2] + sacc[nb][3];
        }
        sum0 += __shfl_xor_sync(0xFFFFFFFF, sum0, 1);
        sum0 += __shfl_xor_sync(0xFFFFFFFF, sum0, 2);
        sum1 += __shfl_xor_sync(0xFFFFFFFF, sum1, 1);
        sum1 += __shfl_xor_sync(0xFFFFFFFF, sum1, 2);
        l0 = l0 * al0 + sum0;
        l1 = l1 * al1 + sum1;
        m0 = mn0;
        m1 = mn1;

        // ---- rescale O, accumulate P @ V ----
#pragma unroll
        for (int nb = 0; nb < 8; nb++) {
            oacc[nb][0] *= al0; oacc[nb][1] *= al0;
            oacc[nb][2] *= al1; oacc[nb][3] *= al1;
        }
#pragma unroll
        for (int kk = 0; kk < 4; kk++) {
            const int k0 = kk * 16;
            uint32_t pa[4];
            pa[0] = pack_h2(sacc[2 * kk][0],     sacc[2 * kk][1]);
            pa[1] = pack_h2(sacc[2 * kk][2],     sacc[2 * kk][3]);
            pa[2] = pack_h2(sacc[2 * kk + 1][0], sacc[2 * kk + 1][1]);
            pa[3] = pack_h2(sacc[2 * kk + 1][2], sacc[2 * kk + 1][3]);
#pragma unroll
            for (int nb = 0; nb < 8; nb++) {
                uint32_t b0 = *(const uint32_t*)&sV[(nb * 8 + lr) * KSTR + k0 + lk];
                uint32_t b1 = *(const uint32_t*)&sV[(nb * 8 + lr) * KSTR + k0 + lk + 8];
                mma_f16(oacc[nb], pa, b0, b1);
            }
        }
        __syncthreads();
    }

    // ---- normalize + write fp16 output [b][s][h][d] ----
    const float inv0 = 1.f / l0;
    const float inv1 = 1.f / l1;
#pragma unroll
    for (int nb = 0; nb < 8; nb++) {
        int c = nb * 8 + lk;
        size_t o0 = ((size_t)(b * SEQ + qt * 128 + wm + lr) * NHEAD + h) * HDIM + c;
        size_t o1 = ((size_t)(b * SEQ + qt * 128 + wm + lr + 8) * NHEAD + h) * HDIM + c;
        *(__half2*)(og + o0) = __floats2half2_rn(oacc[nb][0] * inv0,
                                                 oacc[nb][1] * inv0);
        *(__half2*)(og + o1) = __floats2half2_rn(oacc[nb][2] * inv1,
                                                 oacc[nb][3] * inv1);
    }
}

// ---------------------------------------------------------------------------
// Host launcher
// Inputs: 0 hidden 1 cos 2 sin 3 mask(unused) 4 Wq 5 Wk 6 Wv 7 Wo
// ---------------------------------------------------------------------------
extern "C" void kernel_launch(void* const* d_in, const int* in_sizes, int n_in,
                              void* d_out, int out_size) {
    const float* hidden = (const float*)d_in[0];
    const float* cosb   = (const float*)d_in[1];
    const float* sinb   = (const float*)d_in[2];
    const float* Wq     = (const float*)d_in[4];
    const float* Wk     = (const float*)d_in[5];
    const float* Wv     = (const float*)d_in[6];
    const float* Wo     = (const float*)d_in[7];
    float* out = (float*)d_out;

    float *qp, *kp, *vp;
    cudaGetSymbolAddress((void**)&qp, g_q);
    cudaGetSymbolAddress((void**)&kp, g_k);
    cudaGetSymbolAddress((void**)&vp, g_v);

    __half *a16, *o16, *w16q, *w16k, *w16v, *w16o, *qhp, *khp, *vhtp;
    cudaGetSymbolAddress((void**)&a16, g_a16);
    cudaGetSymbolAddress((void**)&o16, g_o16);
    cudaGetSymbolAddress((void**)&w16q, g_w16q);
    cudaGetSymbolAddress((void**)&w16k, g_w16k);
    cudaGetSymbolAddress((void**)&w16v, g_w16v);
    cudaGetSymbolAddress((void**)&w16o, g_w16o);
    cudaGetSymbolAddress((void**)&qhp, g_qh);
    cudaGetSymbolAddress((void**)&khp, g_kh);
    cudaGetSymbolAddress((void**)&vhtp, g_vht);

    const int M = NBATCH * SEQ;  // 4096

    cudaFuncSetAttribute(gemm_mma16, cudaFuncAttributeMaxDynamicSharedMemorySize,
                         GEMM_SMEM);
    cudaFuncSetAttribute(flash_tc, cudaFuncAttributeMaxDynamicSharedMemorySize,
                         FLASH_SMEM);

    // Operand conversions (all single fp16)
    int n4h = (M * HID) / 4;
    tohalf_kernel<<<(n4h + 255) / 256, 256>>>(hidden, a16, n4h, 1.f);
    int n4q = (2048 * 2048) / 4;
    tohalf_kernel<<<(n4q + 255) / 256, 256>>>(Wq, w16q, n4q, 1.f);
    tohalf_kernel<<<(n4q + 255) / 256, 256>>>(Wo, w16o, n4q, 1.f);
    int n4k = (512 * 2048) / 4;
    tohalf_kernel<<<(n4k + 255) / 256, 256>>>(Wk, w16k, n4k, 1.f);
    tohalf_kernel<<<(n4k + 255) / 256, 256>>>(Wv, w16v, n4k, 1.f);

    // QKV projections (fp16 single-term, fp32 out)
    gemm_mma16<<<dim3(2048 / 128, M / 128), 256, GEMM_SMEM>>>(a16, w16q, qp, M, 2048, 2048);
    gemm_mma16<<<dim3(512  / 128, M / 128), 256, GEMM_SMEM>>>(a16, w16k, kp, M, 512, 2048);
    gemm_mma16<<<dim3(512  / 128, M / 128), 256, GEMM_SMEM>>>(a16, w16v, vp, M, 512, 2048);

    // Fused RoPE + scale + fp16 convert (Q scaled by 1/sqrt(D))
    int tq4 = M * NHEAD * 16;
    rope_half_kernel<<<(tq4 + 255) / 256, 256>>>(qp, cosb, sinb, qhp, NHEAD, tq4, 0.125f);
    int tk4 = M * NKV * 16;
    rope_half_kernel<<<(tk4 + 255) / 256, 256>>>(kp, cosb, sinb, khp, NKV, tk4, 1.f);

    vT_half_kernel<<<dim3(SEQ / 32, HDIM / 32, NBATCH * NKV), dim3(32, 8)>>>(vp, vhtp);

    // Register-softmax flash attention, 128-row Q tiles, 8 warps
    flash_tc<<<dim3(SEQ / 128, NBATCH * NHEAD), 256, FLASH_SMEM>>>(qhp, khp, vhtp, o16);

    // Output projection (fp16 single-term)
    gemm_mma16<<<dim3(2048 / 128, M / 128), 256, GEMM_SMEM>>>(o16, w16o, out, M, 2048, 2048);
}